// round 1
// baseline (speedup 1.0000x reference)
#include <cuda_runtime.h>
#include <cstddef>

#define TT 4
#define BB 4
#define CC 384
#define HH 64
#define WW 64
#define NN (HH*WW)          // 4096
#define IMG (TT*BB)         // 16
#define BCN (BB*CC*NN)      // 6291456 (alif stride over t)
#define HEADS 6
#define DH 64
#define PADW 66
#define EPS 1e-5f

// ---------------- scratch (static device globals; no allocation) ----------------
__device__ float g_XS [IMG*CC*NN];        // spikes of x
__device__ float g_PAD[IMG*CC*PADW*PADW]; // bn1+pad output (66x66)
__device__ float g_DW [IMG*CC*NN];        // depthwise output
__device__ float g_BR [IMG*CC*NN];        // branch output (pre-alif) / attention a
__device__ float g_QS [IMG*CC*NN];
__device__ float g_KS [IMG*CC*NN];
__device__ float g_VS [IMG*CC*NN];
__device__ float g_AS [IMG*CC*NN];        // spikes of attention output
__device__ float g_KV [TT*BB*HEADS*DH*DH];

// ---------------- ALIF scan over T ----------------
// buffers laid out [T*B][C][N]; fixed (b,c,n) has stride BCN over t.
__global__ void alif_kernel(const float* __restrict__ in, float* __restrict__ out,
                            const float* __restrict__ vth_ptr, int vidx) {
    int j = blockIdx.x * blockDim.x + threadIdx.x;
    if (j >= BCN) return;
    float vth = vth_ptr[vidx];
    float v = 0.0f;
#pragma unroll
    for (int t = 0; t < TT; t++) {
        float x = in[j + t * BCN];
        v = v + (x - v) * 0.5f;                 // TAU = 2
        out[j + t * BCN] = (v - vth >= 0.0f) ? 1.0f : 0.0f;
    }
}

// ---------------- pad border fill: pad_val = b - m*inv ----------------
__global__ void padfill_kernel(float* __restrict__ pad,
                               const float* __restrict__ bw, const float* __restrict__ bb,
                               const float* __restrict__ bm, const float* __restrict__ bv) {
    int ic = blockIdx.x;            // img*CC + c
    int c  = ic % CC;
    int t  = threadIdx.x;
    if (t >= 260) return;
    float inv = bw[c] * rsqrtf(bv[c] + EPS);
    float pv  = bb[c] - bm[c] * inv;
    int r, cl;
    if      (t < 66)  { r = 0;          cl = t;        }
    else if (t < 132) { r = 65;         cl = t - 66;   }
    else if (t < 196) { r = t - 132 + 1; cl = 0;       }
    else              { r = t - 196 + 1; cl = 65;      }
    pad[((size_t)ic * PADW + r) * PADW + cl] = pv;
}

// ---------------- 1x1 conv = GEMM  out[o][p] = sum_c W[o][c] * X[c][p] ----------------
// mode 0: epilogue bn1 (wA..) and write into PAD (66x66, interior)
// mode 1: epilogue bn2(wA..) then bn3(wB..) fused, write [o][p] dense layout
__global__ void conv1x1_kernel(const float* __restrict__ X, const float* __restrict__ W,
                               float* __restrict__ OUT,
                               const float* __restrict__ wA, const float* __restrict__ bA,
                               const float* __restrict__ mA, const float* __restrict__ vA,
                               const float* __restrict__ wB, const float* __restrict__ bBp,
                               const float* __restrict__ mB, const float* __restrict__ vB,
                               int mode) {
    __shared__ float As[32][65];   // As[k][m] = W[o0+m][k0+k]
    __shared__ float Bs[32][64];   // Bs[k][n] = X[k0+k][n0+n]
    int tx = threadIdx.x;
    int o0 = blockIdx.y * 64;
    int n0 = blockIdx.x * 64;
    int img = blockIdx.z;
    const float* Xp = X + (size_t)img * CC * NN;

    int tm = tx >> 4, tn = tx & 15;
    float acc[4][4];
#pragma unroll
    for (int i = 0; i < 4; i++)
#pragma unroll
        for (int j = 0; j < 4; j++) acc[i][j] = 0.0f;

    for (int k0 = 0; k0 < CC; k0 += 32) {
#pragma unroll
        for (int u = 0; u < 8; u++) {
            int e = tx + u * 256;
            int m = e >> 5, k = e & 31;
            As[k][m] = W[(o0 + m) * CC + (k0 + k)];
            int kb = e >> 6, n = e & 63;
            Bs[kb][n] = Xp[(size_t)(k0 + kb) * NN + n0 + n];
        }
        __syncthreads();
#pragma unroll
        for (int k = 0; k < 32; k++) {
            float a0 = As[k][tm * 4 + 0], a1 = As[k][tm * 4 + 1];
            float a2 = As[k][tm * 4 + 2], a3 = As[k][tm * 4 + 3];
            float b0 = Bs[k][tn * 4 + 0], b1 = Bs[k][tn * 4 + 1];
            float b2 = Bs[k][tn * 4 + 2], b3 = Bs[k][tn * 4 + 3];
            acc[0][0] += a0 * b0; acc[0][1] += a0 * b1; acc[0][2] += a0 * b2; acc[0][3] += a0 * b3;
            acc[1][0] += a1 * b0; acc[1][1] += a1 * b1; acc[1][2] += a1 * b2; acc[1][3] += a1 * b3;
            acc[2][0] += a2 * b0; acc[2][1] += a2 * b1; acc[2][2] += a2 * b2; acc[2][3] += a2 * b3;
            acc[3][0] += a3 * b0; acc[3][1] += a3 * b1; acc[3][2] += a3 * b2; acc[3][3] += a3 * b3;
        }
        __syncthreads();
    }

    if (mode == 0) {
#pragma unroll
        for (int i = 0; i < 4; i++) {
            int o = o0 + tm * 4 + i;
            float inv  = wA[o] * rsqrtf(vA[o] + EPS);
            float beta = bA[o] - mA[o] * inv;
#pragma unroll
            for (int j = 0; j < 4; j++) {
                int p = n0 + tn * 4 + j;
                int r = p >> 6, cl = p & 63;
                OUT[(((size_t)img * CC + o) * PADW + (r + 1)) * PADW + (cl + 1)] =
                    acc[i][j] * inv + beta;
            }
        }
    } else {
#pragma unroll
        for (int i = 0; i < 4; i++) {
            int o = o0 + tm * 4 + i;
            float s2 = wA[o] * rsqrtf(vA[o] + EPS);
            float t2 = bA[o] - mA[o] * s2;
            float s3 = wB[o] * rsqrtf(vB[o] + EPS);
            float t3 = bBp[o] - mB[o] * s3;
            float scale = s2 * s3;
            float bias  = t2 * s3 + t3;
#pragma unroll
            for (int j = 0; j < 4; j++) {
                int p = n0 + tn * 4 + j;
                OUT[((size_t)img * CC + o) * NN + p] = acc[i][j] * scale + bias;
            }
        }
    }
}

// ---------------- depthwise 3x3 VALID on 66x66 -> 64x64 ----------------
__global__ void dwconv_kernel(const float* __restrict__ pad, const float* __restrict__ dww,
                              float* __restrict__ out) {
    int img = blockIdx.z, c = blockIdx.y;
    int p = blockIdx.x * blockDim.x + threadIdx.x;   // 0..4095
    int r = p >> 6, cl = p & 63;
    const float* base = pad + ((size_t)img * CC + c) * PADW * PADW;
    const float* w = dww + c * 9;
    float s = 0.0f;
#pragma unroll
    for (int i = 0; i < 3; i++)
#pragma unroll
        for (int j = 0; j < 3; j++)
            s += w[i * 3 + j] * base[(r + i) * PADW + (cl + j)];
    out[((size_t)img * CC + c) * NN + p] = s;
}

// ---------------- kv[tbh][d][e] = sum_n K[tb][h*64+d][n] * V[tb][h*64+e][n] ----------------
__global__ void kv_kernel(const float* __restrict__ K, const float* __restrict__ V,
                          float* __restrict__ KVb) {
    int tbh = blockIdx.x;
    int tb = tbh / HEADS, h = tbh % HEADS;
    __shared__ float Ks[64][65];   // [n][d]
    __shared__ float Vs[64][65];   // [n][e]
    int tx = threadIdx.x;
    int td = tx >> 4, te = tx & 15;
    const float* Kb = K + ((size_t)tb * CC + h * DH) * NN;
    const float* Vb = V + ((size_t)tb * CC + h * DH) * NN;
    float acc[4][4];
#pragma unroll
    for (int i = 0; i < 4; i++)
#pragma unroll
        for (int j = 0; j < 4; j++) acc[i][j] = 0.0f;

    for (int n0 = 0; n0 < NN; n0 += 64) {
#pragma unroll
        for (int u = 0; u < 16; u++) {
            int e = tx + u * 256;
            int d = e >> 6, n = e & 63;
            Ks[n][d] = Kb[(size_t)d * NN + n0 + n];
            Vs[n][d] = Vb[(size_t)d * NN + n0 + n];
        }
        __syncthreads();
#pragma unroll
        for (int n = 0; n < 64; n++) {
            float a0 = Ks[n][td * 4 + 0], a1 = Ks[n][td * 4 + 1];
            float a2 = Ks[n][td * 4 + 2], a3 = Ks[n][td * 4 + 3];
            float b0 = Vs[n][te * 4 + 0], b1 = Vs[n][te * 4 + 1];
            float b2 = Vs[n][te * 4 + 2], b3 = Vs[n][te * 4 + 3];
            acc[0][0] += a0 * b0; acc[0][1] += a0 * b1; acc[0][2] += a0 * b2; acc[0][3] += a0 * b3;
            acc[1][0] += a1 * b0; acc[1][1] += a1 * b1; acc[1][2] += a1 * b2; acc[1][3] += a1 * b3;
            acc[2][0] += a2 * b0; acc[2][1] += a2 * b1; acc[2][2] += a2 * b2; acc[2][3] += a2 * b3;
            acc[3][0] += a3 * b0; acc[3][1] += a3 * b1; acc[3][2] += a3 * b2; acc[3][3] += a3 * b3;
        }
        __syncthreads();
    }
#pragma unroll
    for (int i = 0; i < 4; i++)
#pragma unroll
        for (int j = 0; j < 4; j++)
            KVb[(size_t)tbh * DH * DH + (td * 4 + i) * DH + (te * 4 + j)] = acc[i][j];
}

// ---------------- A[tb][h*64+e][n] = sum_d Q[tb][h*64+d][n] * KV[tbh][d][e] ----------------
__global__ void av_kernel(const float* __restrict__ Q, const float* __restrict__ KVb,
                          float* __restrict__ A) {
    int nt = blockIdx.x;      // 64 n-tiles of 64
    int tbh = blockIdx.y;
    int tb = tbh / HEADS, h = tbh % HEADS;
    __shared__ float kvs[64][65];  // [d][e]
    __shared__ float Qs[64][65];   // [d][n]
    int tx = threadIdx.x;
    int te = tx >> 4, tn = tx & 15;
    int n0 = nt * 64;
    const float* Qb = Q + ((size_t)tb * CC + h * DH) * NN;
#pragma unroll
    for (int u = 0; u < 16; u++) {
        int e = tx + u * 256;
        int d = e >> 6, x = e & 63;
        kvs[d][x] = KVb[(size_t)tbh * DH * DH + d * DH + x];
        Qs[d][x]  = Qb[(size_t)d * NN + n0 + x];
    }
    __syncthreads();
    float acc[4][4];
#pragma unroll
    for (int i = 0; i < 4; i++)
#pragma unroll
        for (int j = 0; j < 4; j++) acc[i][j] = 0.0f;
#pragma unroll
    for (int d = 0; d < 64; d++) {
        float a0 = kvs[d][te * 4 + 0], a1 = kvs[d][te * 4 + 1];
        float a2 = kvs[d][te * 4 + 2], a3 = kvs[d][te * 4 + 3];
        float b0 = Qs[d][tn * 4 + 0], b1 = Qs[d][tn * 4 + 1];
        float b2 = Qs[d][tn * 4 + 2], b3 = Qs[d][tn * 4 + 3];
        acc[0][0] += a0 * b0; acc[0][1] += a0 * b1; acc[0][2] += a0 * b2; acc[0][3] += a0 * b3;
        acc[1][0] += a1 * b0; acc[1][1] += a1 * b1; acc[1][2] += a1 * b2; acc[1][3] += a1 * b3;
        acc[2][0] += a2 * b0; acc[2][1] += a2 * b1; acc[2][2] += a2 * b2; acc[2][3] += a2 * b3;
        acc[3][0] += a3 * b0; acc[3][1] += a3 * b1; acc[3][2] += a3 * b2; acc[3][3] += a3 * b3;
    }
#pragma unroll
    for (int i = 0; i < 4; i++) {
        int e = te * 4 + i;
#pragma unroll
        for (int j = 0; j < 4; j++) {
            int n = tn * 4 + j;
            A[((size_t)tb * CC + h * DH + e) * NN + n0 + n] = acc[i][j];
        }
    }
}

// ---------------- host orchestration ----------------
static void run_branch(const float* in, int i, float* out,
                       const float* w1, const float* dw, const float* pw,
                       const float* b1w, const float* b1b, const float* b1m, const float* b1v,
                       const float* b2w, const float* b2b, const float* b2m, const float* b2v,
                       const float* b3w, const float* b3b, const float* b3m, const float* b3v,
                       float* PAD, float* DWB) {
    padfill_kernel<<<IMG * CC, 288>>>(PAD, b1w + i * CC, b1b + i * CC, b1m + i * CC, b1v + i * CC);
    conv1x1_kernel<<<dim3(64, 6, IMG), 256>>>(in, w1 + (size_t)i * CC * CC, PAD,
        b1w + i * CC, b1b + i * CC, b1m + i * CC, b1v + i * CC,
        nullptr, nullptr, nullptr, nullptr, 0);
    dwconv_kernel<<<dim3(16, CC, IMG), 256>>>(PAD, dw + (size_t)i * CC * 9, DWB);
    conv1x1_kernel<<<dim3(64, 6, IMG), 256>>>(DWB, pw + (size_t)i * CC * CC, out,
        b2w + i * CC, b2b + i * CC, b2m + i * CC, b2v + i * CC,
        b3w + i * CC, b3b + i * CC, b3m + i * CC, b3v + i * CC, 1);
}

extern "C" void kernel_launch(void* const* d_in, const int* in_sizes, int n_in,
                              void* d_out, int out_size) {
    const float* x   = (const float*)d_in[0];
    const float* w1  = (const float*)d_in[1];
    const float* dw  = (const float*)d_in[2];
    const float* pw  = (const float*)d_in[3];
    const float* b1w = (const float*)d_in[4];
    const float* b1b = (const float*)d_in[5];
    const float* b1m = (const float*)d_in[6];
    const float* b1v = (const float*)d_in[7];
    const float* b2w = (const float*)d_in[8];
    const float* b2b = (const float*)d_in[9];
    const float* b2m = (const float*)d_in[10];
    const float* b2v = (const float*)d_in[11];
    const float* b3w = (const float*)d_in[12];
    const float* b3b = (const float*)d_in[13];
    const float* b3m = (const float*)d_in[14];
    const float* b3v = (const float*)d_in[15];
    const float* vth = (const float*)d_in[16];
    float* out = (float*)d_out;

    float *XS, *PAD, *DWB, *BR, *QS, *KS, *VS, *AS, *KV;
    cudaGetSymbolAddress((void**)&XS,  g_XS);
    cudaGetSymbolAddress((void**)&PAD, g_PAD);
    cudaGetSymbolAddress((void**)&DWB, g_DW);
    cudaGetSymbolAddress((void**)&BR,  g_BR);
    cudaGetSymbolAddress((void**)&QS,  g_QS);
    cudaGetSymbolAddress((void**)&KS,  g_KS);
    cudaGetSymbolAddress((void**)&VS,  g_VS);
    cudaGetSymbolAddress((void**)&AS,  g_AS);
    cudaGetSymbolAddress((void**)&KV,  g_KV);

    const int athreads = 256;
    const int ablocks = (BCN + athreads - 1) / athreads;

    // 1) alif on x
    alif_kernel<<<ablocks, athreads>>>(x, XS, vth, 0);

    // 2) q/k/v branches
    float* sp[3] = {QS, KS, VS};
    for (int i = 0; i < 3; i++) {
        run_branch(XS, i, BR, w1, dw, pw,
                   b1w, b1b, b1m, b1v, b2w, b2b, b2m, b2v, b3w, b3b, b3m, b3v, PAD, DWB);
        alif_kernel<<<ablocks, athreads>>>(BR, sp[i], vth, 1 + i);
    }

    // 3) attention
    kv_kernel<<<TT * BB * HEADS, 256>>>(KS, VS, KV);
    av_kernel<<<dim3(64, TT * BB * HEADS), 256>>>(QS, KV, BR);
    alif_kernel<<<ablocks, athreads>>>(BR, AS, vth, 4);

    // 4) final branch writes directly to d_out (layout identical)
    run_branch(AS, 3, out, w1, dw, pw,
               b1w, b1b, b1m, b1v, b2w, b2b, b2m, b2v, b3w, b3b, b3m, b3v, PAD, DWB);
}

// round 4
// speedup vs baseline: 1.1975x; 1.1975x over previous
#include <cuda_runtime.h>
#include <cstdint>
#include <cstddef>

#define TT 4
#define BB 4
#define CC 384
#define NN 4096
#define IMG 16
#define BCN (BB*CC*NN)
#define HEADS 6
#define DH 64
#define PADW 66
#define EPS 1e-5f

// ---------------- scratch (static device globals) ----------------
__device__ __align__(256) float g_XS [IMG*NN*CC];         // spikes of x (NHWC)
__device__ __align__(256) float g_PAD[IMG*PADW*PADW*CC];  // bn1+pad (NHWC, 66x66)
__device__ __align__(256) float g_DW [IMG*NN*CC];         // depthwise out (NHWC)
__device__ __align__(256) float g_BR [IMG*NN*CC];         // branch out / attention a (NHWC)
__device__ __align__(256) float g_QS [IMG*NN*CC];
__device__ __align__(256) float g_KS [IMG*NN*CC];
__device__ __align__(256) float g_VS [IMG*NN*CC];
__device__ __align__(256) float g_AS [IMG*NN*CC];
__device__ __align__(256) float g_KVP[4*TT*BB*HEADS*DH*DH];
__device__ __align__(256) float g_KV [TT*BB*HEADS*DH*DH];

__device__ __forceinline__ float tf32r(float x) {
    uint32_t u;
    asm("cvt.rna.tf32.f32 %0, %1;" : "=r"(u) : "f"(x));
    return __uint_as_float(u);
}
__device__ __forceinline__ void mma8(float* c, uint32_t a0, uint32_t a1, uint32_t a2, uint32_t a3,
                                     uint32_t b0, uint32_t b1) {
    asm volatile("mma.sync.aligned.m16n8k8.row.col.f32.tf32.tf32.f32 "
                 "{%0,%1,%2,%3}, {%4,%5,%6,%7}, {%8,%9}, {%0,%1,%2,%3};"
                 : "+f"(c[0]), "+f"(c[1]), "+f"(c[2]), "+f"(c[3])
                 : "r"(a0), "r"(a1), "r"(a2), "r"(a3), "r"(b0), "r"(b1));
}

// smem word layout (floats). ROWS_W MUST be even (8B-aligned float2 smem loads);
// 40 gives conflict-free lds.64 fragment loads (lr*40+2*lc mod 32 = lr*8+2*lc, all distinct).
#define ROWS_W 40
#define SA_H 0
#define SA_L (128*ROWS_W)       // 5120
#define SB_H (2*128*ROWS_W)     // 10240
#define SB_L (3*128*ROWS_W)     // 15360
#define SCL  (4*128*ROWS_W)     // 20480
#define SBS  (SCL+128)          // 20608
#define SMEM_FLOATS (SBS+128)   // 20736
#define SMEM_BYTES  (SMEM_FLOATS*4)

// k permutation within each 8-block: pairs (k, k+4) adjacent.
// global k = q*4+i (q=0..7 quad, i component) -> word = (q>>1)*8 + 2*i + (q&1)
__device__ __forceinline__ int kperm(int q, int i) { return ((q >> 1) << 3) + (i << 1) + (q & 1); }

// ---------------- mma.sync tf32 split-precision conv1x1 ----------------
// D[p][o] = sum_c X[p][c] * W[o][c]  (M=128 spatial tile, N=128 outch tile, K=384)
// mode 0: binary input (2 passes), bn1 epilogue, write PAD interior (NHWC)
// mode 1: dense input (3 passes), bn2*bn3 epilogue, write NHWC
// mode 2: dense input (3 passes), bn2*bn3 epilogue, write NCHW (d_out)
__global__ void __launch_bounds__(256, 1)
conv_mma_kernel(const float* __restrict__ X, const float* __restrict__ W,
                float* __restrict__ OUT,
                const float* __restrict__ wA, const float* __restrict__ bA,
                const float* __restrict__ mA, const float* __restrict__ vA,
                const float* __restrict__ wB, const float* __restrict__ bB2,
                const float* __restrict__ mB, const float* __restrict__ vB,
                int mode) {
    extern __shared__ float sm[];
    int tx = threadIdx.x;
    int wid = tx >> 5, lane = tx & 31;
    int lr = lane >> 2, lc = lane & 3;
    int wm = wid & 1, wn = wid >> 1;        // warp grid 2(m) x 4(n)
    int img = blockIdx.z;
    int p0 = blockIdx.x * 128;
    int n0 = blockIdx.y * 128;

    // fused BN scale/bias (for this CTA's 128 out-channels)
    if (tx < 128) {
        int o = n0 + tx;
        float s, bias;
        if (mode == 0) {
            float inv = wA[o] * rsqrtf(vA[o] + EPS);
            s = inv; bias = bA[o] - mA[o] * inv;
        } else {
            float s2 = wA[o] * rsqrtf(vA[o] + EPS);
            float t2 = bA[o] - mA[o] * s2;
            float s3 = wB[o] * rsqrtf(vB[o] + EPS);
            float t3 = bB2[o] - mB[o] * s3;
            s = s2 * s3; bias = t2 * s3 + t3;
        }
        sm[SCL + tx] = s;
        sm[SBS + tx] = bias;
    }

    const float* Xp = X + ((size_t)img * NN + p0) * CC;
    const float* Wp = W + (size_t)n0 * CC;
    bool dense = (mode != 0);

    float acc[4][4][4];
#pragma unroll
    for (int a = 0; a < 4; a++)
#pragma unroll
        for (int b = 0; b < 4; b++)
#pragma unroll
            for (int c = 0; c < 4; c++) acc[a][b][c] = 0.0f;

    for (int ch = 0; ch < 12; ch++) {
        int c0 = ch * 32;
        // ---- load B (weights) 128 rows x 32 k, split hi/lo ----
#pragma unroll
        for (int it = 0; it < 4; it++) {
            int u = tx + it * 256;
            int row = u >> 3, q = u & 7;
            float4 v = *(const float4*)(Wp + (size_t)row * CC + c0 + q * 4);
            float h, l;
            h = tf32r(v.x); l = tf32r(v.x - h);
            sm[SB_H + row * ROWS_W + kperm(q, 0)] = h; sm[SB_L + row * ROWS_W + kperm(q, 0)] = l;
            h = tf32r(v.y); l = tf32r(v.y - h);
            sm[SB_H + row * ROWS_W + kperm(q, 1)] = h; sm[SB_L + row * ROWS_W + kperm(q, 1)] = l;
            h = tf32r(v.z); l = tf32r(v.z - h);
            sm[SB_H + row * ROWS_W + kperm(q, 2)] = h; sm[SB_L + row * ROWS_W + kperm(q, 2)] = l;
            h = tf32r(v.w); l = tf32r(v.w - h);
            sm[SB_H + row * ROWS_W + kperm(q, 3)] = h; sm[SB_L + row * ROWS_W + kperm(q, 3)] = l;
        }
        // ---- load A (activations) 128 rows x 32 k ----
#pragma unroll
        for (int it = 0; it < 4; it++) {
            int u = tx + it * 256;
            int row = u >> 3, q = u & 7;
            float4 v = *(const float4*)(Xp + (size_t)row * CC + c0 + q * 4);
            if (!dense) {
                sm[SA_H + row * ROWS_W + kperm(q, 0)] = v.x;
                sm[SA_H + row * ROWS_W + kperm(q, 1)] = v.y;
                sm[SA_H + row * ROWS_W + kperm(q, 2)] = v.z;
                sm[SA_H + row * ROWS_W + kperm(q, 3)] = v.w;
            } else {
                float h, l;
                h = tf32r(v.x); l = tf32r(v.x - h);
                sm[SA_H + row * ROWS_W + kperm(q, 0)] = h; sm[SA_L + row * ROWS_W + kperm(q, 0)] = l;
                h = tf32r(v.y); l = tf32r(v.y - h);
                sm[SA_H + row * ROWS_W + kperm(q, 1)] = h; sm[SA_L + row * ROWS_W + kperm(q, 1)] = l;
                h = tf32r(v.z); l = tf32r(v.z - h);
                sm[SA_H + row * ROWS_W + kperm(q, 2)] = h; sm[SA_L + row * ROWS_W + kperm(q, 2)] = l;
                h = tf32r(v.w); l = tf32r(v.w - h);
                sm[SA_H + row * ROWS_W + kperm(q, 3)] = h; sm[SA_L + row * ROWS_W + kperm(q, 3)] = l;
            }
        }
        __syncthreads();

#pragma unroll
        for (int kk = 0; kk < 4; kk++) {
            int kb = kk * 8 + 2 * lc;
            uint32_t A0[4], A1[4], A2[4], A3[4];
#pragma unroll
            for (int mt = 0; mt < 4; mt++) {
                int r = wm * 64 + mt * 16 + lr;
                float2 u0 = *(float2*)&sm[SA_H + r * ROWS_W + kb];
                float2 u1 = *(float2*)&sm[SA_H + (r + 8) * ROWS_W + kb];
                A0[mt] = __float_as_uint(u0.x); A2[mt] = __float_as_uint(u0.y);
                A1[mt] = __float_as_uint(u1.x); A3[mt] = __float_as_uint(u1.y);
            }
            uint32_t Bh0[4], Bh1[4], Bl0[4], Bl1[4];
#pragma unroll
            for (int nt = 0; nt < 4; nt++) {
                int n = wn * 32 + nt * 8 + lr;
                float2 vh = *(float2*)&sm[SB_H + n * ROWS_W + kb];
                float2 vl = *(float2*)&sm[SB_L + n * ROWS_W + kb];
                Bh0[nt] = __float_as_uint(vh.x); Bh1[nt] = __float_as_uint(vh.y);
                Bl0[nt] = __float_as_uint(vl.x); Bl1[nt] = __float_as_uint(vl.y);
            }
#pragma unroll
            for (int mt = 0; mt < 4; mt++)
#pragma unroll
                for (int nt = 0; nt < 4; nt++)
                    mma8(acc[mt][nt], A0[mt], A1[mt], A2[mt], A3[mt], Bh0[nt], Bh1[nt]);
#pragma unroll
            for (int mt = 0; mt < 4; mt++)
#pragma unroll
                for (int nt = 0; nt < 4; nt++)
                    mma8(acc[mt][nt], A0[mt], A1[mt], A2[mt], A3[mt], Bl0[nt], Bl1[nt]);
            if (dense) {
#pragma unroll
                for (int mt = 0; mt < 4; mt++) {
                    int r = wm * 64 + mt * 16 + lr;
                    float2 u0 = *(float2*)&sm[SA_L + r * ROWS_W + kb];
                    float2 u1 = *(float2*)&sm[SA_L + (r + 8) * ROWS_W + kb];
                    A0[mt] = __float_as_uint(u0.x); A2[mt] = __float_as_uint(u0.y);
                    A1[mt] = __float_as_uint(u1.x); A3[mt] = __float_as_uint(u1.y);
                }
#pragma unroll
                for (int mt = 0; mt < 4; mt++)
#pragma unroll
                    for (int nt = 0; nt < 4; nt++)
                        mma8(acc[mt][nt], A0[mt], A1[mt], A2[mt], A3[mt], Bh0[nt], Bh1[nt]);
            }
        }
        __syncthreads();
    }

    // ---------------- epilogue ----------------
    if (mode != 2) {
#pragma unroll
        for (int mt = 0; mt < 4; mt++) {
            int pa = p0 + wm * 64 + mt * 16 + lr;
            int pb = pa + 8;
#pragma unroll
            for (int nt = 0; nt < 4; nt++) {
                int ol = wn * 32 + nt * 8 + 2 * lc;
                float s0 = sm[SCL + ol], s1 = sm[SCL + ol + 1];
                float z0 = sm[SBS + ol], z1 = sm[SBS + ol + 1];
                float2 v0 = make_float2(acc[mt][nt][0] * s0 + z0, acc[mt][nt][1] * s1 + z1);
                float2 v1 = make_float2(acc[mt][nt][2] * s0 + z0, acc[mt][nt][3] * s1 + z1);
                if (mode == 0) {
                    int ra = pa >> 6, ca = pa & 63;
                    int rb = pb >> 6, cb = pb & 63;
                    *(float2*)(OUT + ((((size_t)img * PADW + ra + 1) * PADW + ca + 1) * CC) + n0 + ol) = v0;
                    *(float2*)(OUT + ((((size_t)img * PADW + rb + 1) * PADW + cb + 1) * CC) + n0 + ol) = v1;
                } else {
                    *(float2*)(OUT + ((size_t)img * NN + pa) * CC + n0 + ol) = v0;
                    *(float2*)(OUT + ((size_t)img * NN + pb) * CC + n0 + ol) = v1;
                }
            }
        }
    } else {
        // NCHW output: stage per-warp 32(n) x 64(m) tile in smem, then coalesced rows
        float* T = sm + wid * (32 * 66);
#pragma unroll
        for (int mt = 0; mt < 4; mt++) {
            int ma = mt * 16 + lr;
#pragma unroll
            for (int nt = 0; nt < 4; nt++) {
                int nl = nt * 8 + 2 * lc;
                int ol = wn * 32 + nl;
                float s0 = sm[SCL + ol], s1 = sm[SCL + ol + 1];
                float z0 = sm[SBS + ol], z1 = sm[SBS + ol + 1];
                T[nl * 66 + ma]           = acc[mt][nt][0] * s0 + z0;
                T[(nl + 1) * 66 + ma]     = acc[mt][nt][1] * s1 + z1;
                T[nl * 66 + ma + 8]       = acc[mt][nt][2] * s0 + z0;
                T[(nl + 1) * 66 + ma + 8] = acc[mt][nt][3] * s1 + z1;
            }
        }
        __syncwarp();
#pragma unroll
        for (int ol = 0; ol < 32; ol++) {
            int o = n0 + wn * 32 + ol;
            float2 v = make_float2(T[ol * 66 + lane * 2], T[ol * 66 + lane * 2 + 1]);
            *(float2*)(OUT + ((size_t)img * CC + o) * NN + p0 + wm * 64 + lane * 2) = v;
        }
    }
}

// ---------------- ALIF: first (NCHW in -> NHWC spikes out, transpose) ----------------
__global__ void alif_first_kernel(const float* __restrict__ in, float* __restrict__ out,
                                  const float* __restrict__ vth_ptr) {
    __shared__ float s[32][33];
    int tx = threadIdx.x, ty = threadIdx.y;
    int n0 = blockIdx.x * 32;
    int c0 = blockIdx.y * 32;
    int b = blockIdx.z;
    float vth = vth_ptr[0];
    float v[4] = {0.f, 0.f, 0.f, 0.f};
#pragma unroll
    for (int t = 0; t < TT; t++) {
#pragma unroll
        for (int k = 0; k < 4; k++) {
            int c = c0 + ty + 8 * k;
            float xv = in[(((size_t)(t * BB + b) * CC + c) * NN) + n0 + tx];
            v[k] = v[k] + (xv - v[k]) * 0.5f;
            s[ty + 8 * k][tx] = (v[k] - vth >= 0.0f) ? 1.0f : 0.0f;
        }
        __syncthreads();
#pragma unroll
        for (int k = 0; k < 4; k++) {
            int n = n0 + ty + 8 * k;
            out[((size_t)(t * BB + b) * NN + n) * CC + c0 + tx] = s[tx][ty + 8 * k];
        }
        __syncthreads();
    }
}

// ---------------- ALIF generic (elementwise scan over t) ----------------
__global__ void alif_kernel(const float* __restrict__ in, float* __restrict__ out,
                            const float* __restrict__ vth_ptr, int vidx) {
    int j = blockIdx.x * blockDim.x + threadIdx.x;
    if (j >= BCN) return;
    float vth = vth_ptr[vidx];
    float v = 0.0f;
#pragma unroll
    for (int t = 0; t < TT; t++) {
        float x = in[(size_t)j + (size_t)t * BCN];
        v = v + (x - v) * 0.5f;
        out[(size_t)j + (size_t)t * BCN] = (v - vth >= 0.0f) ? 1.0f : 0.0f;
    }
}

// ---------------- pad border fill (NHWC) ----------------
__global__ void padfill_kernel(float* __restrict__ pad,
                               const float* __restrict__ bw, const float* __restrict__ bb,
                               const float* __restrict__ bm, const float* __restrict__ bv) {
    int t = blockIdx.x;
    int img = blockIdx.y;
    int c = threadIdx.x;
    float inv = bw[c] * rsqrtf(bv[c] + EPS);
    float pv = bb[c] - bm[c] * inv;
    int r, cl;
    if      (t < 66)  { r = 0;           cl = t;        }
    else if (t < 132) { r = 65;          cl = t - 66;   }
    else if (t < 196) { r = t - 132 + 1; cl = 0;        }
    else              { r = t - 196 + 1; cl = 65;       }
    pad[(((size_t)img * PADW + r) * PADW + cl) * CC + c] = pv;
}

// ---------------- depthwise 3x3 VALID (NHWC) ----------------
__global__ void dwconv_kernel(const float* __restrict__ pad, const float* __restrict__ w9,
                              float* __restrict__ out) {
    int c = threadIdx.x;
    int p = blockIdx.x;
    int img = blockIdx.y;
    int r = p >> 6, cl = p & 63;
    const float* base = pad + (((size_t)img * PADW + r) * PADW + cl) * CC + c;
    float wr[9];
#pragma unroll
    for (int k = 0; k < 9; k++) wr[k] = __ldg(w9 + c * 9 + k);
    float sacc = 0.0f;
#pragma unroll
    for (int i = 0; i < 3; i++)
#pragma unroll
        for (int j = 0; j < 3; j++)
            sacc += wr[i * 3 + j] * base[(size_t)(i * PADW + j) * CC];
    out[((size_t)img * NN + p) * CC + c] = sacc;
}

// ---------------- kv partial (NHWC): kvp[seg][tbh][d][e] ----------------
__global__ void kv_kernel(const float* __restrict__ K, const float* __restrict__ V,
                          float* __restrict__ KVP) {
    int seg = blockIdx.x;
    int tbh = blockIdx.y;
    int tb = tbh / HEADS, h = tbh % HEADS;
    __shared__ float Ks[64][65];
    __shared__ float Vs[64][65];
    int tx = threadIdx.x;
    int td = tx >> 4, te = tx & 15;
    const float* Kb = K + (size_t)tb * NN * CC + h * DH;
    const float* Vb = V + (size_t)tb * NN * CC + h * DH;
    float acc[4][4];
#pragma unroll
    for (int i = 0; i < 4; i++)
#pragma unroll
        for (int j = 0; j < 4; j++) acc[i][j] = 0.0f;

    for (int n0 = seg * 1024; n0 < (seg + 1) * 1024; n0 += 64) {
#pragma unroll
        for (int u = 0; u < 16; u++) {
            int e = tx + u * 256;
            int n = e >> 6, d = e & 63;
            Ks[n][d] = Kb[(size_t)(n0 + n) * CC + d];
            Vs[n][d] = Vb[(size_t)(n0 + n) * CC + d];
        }
        __syncthreads();
#pragma unroll
        for (int n = 0; n < 64; n++) {
            float a0 = Ks[n][td * 4 + 0], a1 = Ks[n][td * 4 + 1];
            float a2 = Ks[n][td * 4 + 2], a3 = Ks[n][td * 4 + 3];
            float b0 = Vs[n][te * 4 + 0], b1 = Vs[n][te * 4 + 1];
            float b2 = Vs[n][te * 4 + 2], b3 = Vs[n][te * 4 + 3];
            acc[0][0] += a0 * b0; acc[0][1] += a0 * b1; acc[0][2] += a0 * b2; acc[0][3] += a0 * b3;
            acc[1][0] += a1 * b0; acc[1][1] += a1 * b1; acc[1][2] += a1 * b2; acc[1][3] += a1 * b3;
            acc[2][0] += a2 * b0; acc[2][1] += a2 * b1; acc[2][2] += a2 * b2; acc[2][3] += a2 * b3;
            acc[3][0] += a3 * b0; acc[3][1] += a3 * b1; acc[3][2] += a3 * b2; acc[3][3] += a3 * b3;
        }
        __syncthreads();
    }
#pragma unroll
    for (int i = 0; i < 4; i++)
#pragma unroll
        for (int j = 0; j < 4; j++)
            KVP[((size_t)seg * (TT * BB * HEADS) + tbh) * (DH * DH) + (td * 4 + i) * DH + te * 4 + j] =
                acc[i][j];
}

__global__ void kvred_kernel(const float* __restrict__ KVP, float* __restrict__ KV) {
    int idx = blockIdx.x * blockDim.x + threadIdx.x;
    const int tot = TT * BB * HEADS * DH * DH;
    if (idx >= tot) return;
    float s = 0.f;
#pragma unroll
    for (int g = 0; g < 4; g++) s += KVP[(size_t)g * tot + idx];
    KV[idx] = s;
}

// ---------------- av (NHWC): A[tb][n][h*64+e] = sum_d Q[tb][n][h*64+d]*KV[tbh][d][e] ----------------
__global__ void av_kernel(const float* __restrict__ Q, const float* __restrict__ KV,
                          float* __restrict__ A) {
    int nt = blockIdx.x;
    int tbh = blockIdx.y;
    int tb = tbh / HEADS, h = tbh % HEADS;
    __shared__ float kvs[64][65];
    __shared__ float Qs[64][65];
    int tx = threadIdx.x;
    int tn = tx >> 4, te = tx & 15;
    int n0 = nt * 64;
    const float* Qb = Q + (size_t)tb * NN * CC + h * DH;
#pragma unroll
    for (int u = 0; u < 16; u++) {
        int e = tx + u * 256;
        int r = e >> 6, x = e & 63;
        kvs[r][x] = KV[(size_t)tbh * DH * DH + r * DH + x];
        Qs[r][x] = Qb[(size_t)(n0 + r) * CC + x];
    }
    __syncthreads();
    float acc[4][4];
#pragma unroll
    for (int i = 0; i < 4; i++)
#pragma unroll
        for (int j = 0; j < 4; j++) acc[i][j] = 0.0f;
#pragma unroll
    for (int d = 0; d < 64; d++) {
        float a0 = Qs[tn * 4 + 0][d], a1 = Qs[tn * 4 + 1][d];
        float a2 = Qs[tn * 4 + 2][d], a3 = Qs[tn * 4 + 3][d];
        float b0 = kvs[d][te * 4 + 0], b1 = kvs[d][te * 4 + 1];
        float b2 = kvs[d][te * 4 + 2], b3 = kvs[d][te * 4 + 3];
        acc[0][0] += a0 * b0; acc[0][1] += a0 * b1; acc[0][2] += a0 * b2; acc[0][3] += a0 * b3;
        acc[1][0] += a1 * b0; acc[1][1] += a1 * b1; acc[1][2] += a1 * b2; acc[1][3] += a1 * b3;
        acc[2][0] += a2 * b0; acc[2][1] += a2 * b1; acc[2][2] += a2 * b2; acc[2][3] += a2 * b3;
        acc[3][0] += a3 * b0; acc[3][1] += a3 * b1; acc[3][2] += a3 * b2; acc[3][3] += a3 * b3;
    }
#pragma unroll
    for (int i = 0; i < 4; i++) {
        int n = n0 + tn * 4 + i;
        float4 w4;
        w4.x = acc[i][0]; w4.y = acc[i][1]; w4.z = acc[i][2]; w4.w = acc[i][3];
        *(float4*)(A + ((size_t)tb * NN + n) * CC + h * DH + te * 4) = w4;
    }
}

// ---------------- host orchestration ----------------
static void run_branch(const float* in, int i, float* out, int out_mode,
                       const float* w1, const float* dw, const float* pw,
                       const float* b1w, const float* b1b, const float* b1m, const float* b1v,
                       const float* b2w, const float* b2b, const float* b2m, const float* b2v,
                       const float* b3w, const float* b3b, const float* b3m, const float* b3v,
                       float* PAD, float* DWB) {
    padfill_kernel<<<dim3(260, IMG), CC>>>(PAD, b1w + i * CC, b1b + i * CC, b1m + i * CC, b1v + i * CC);
    conv_mma_kernel<<<dim3(32, 3, IMG), 256, SMEM_BYTES>>>(in, w1 + (size_t)i * CC * CC, PAD,
        b1w + i * CC, b1b + i * CC, b1m + i * CC, b1v + i * CC,
        nullptr, nullptr, nullptr, nullptr, 0);
    dwconv_kernel<<<dim3(NN, IMG), CC>>>(PAD, dw + (size_t)i * CC * 9, DWB);
    conv_mma_kernel<<<dim3(32, 3, IMG), 256, SMEM_BYTES>>>(DWB, pw + (size_t)i * CC * CC, out,
        b2w + i * CC, b2b + i * CC, b2m + i * CC, b2v + i * CC,
        b3w + i * CC, b3b + i * CC, b3m + i * CC, b3v + i * CC, out_mode);
}

extern "C" void kernel_launch(void* const* d_in, const int* in_sizes, int n_in,
                              void* d_out, int out_size) {
    const float* x   = (const float*)d_in[0];
    const float* w1  = (const float*)d_in[1];
    const float* dw  = (const float*)d_in[2];
    const float* pw  = (const float*)d_in[3];
    const float* b1w = (const float*)d_in[4];
    const float* b1b = (const float*)d_in[5];
    const float* b1m = (const float*)d_in[6];
    const float* b1v = (const float*)d_in[7];
    const float* b2w = (const float*)d_in[8];
    const float* b2b = (const float*)d_in[9];
    const float* b2m = (const float*)d_in[10];
    const float* b2v = (const float*)d_in[11];
    const float* b3w = (const float*)d_in[12];
    const float* b3b = (const float*)d_in[13];
    const float* b3m = (const float*)d_in[14];
    const float* b3v = (const float*)d_in[15];
    const float* vth = (const float*)d_in[16];
    float* out = (float*)d_out;

    cudaFuncSetAttribute(conv_mma_kernel, cudaFuncAttributeMaxDynamicSharedMemorySize, SMEM_BYTES);

    float *XS, *PAD, *DWB, *BR, *QS, *KS, *VS, *AS, *KVP, *KV;
    cudaGetSymbolAddress((void**)&XS,  g_XS);
    cudaGetSymbolAddress((void**)&PAD, g_PAD);
    cudaGetSymbolAddress((void**)&DWB, g_DW);
    cudaGetSymbolAddress((void**)&BR,  g_BR);
    cudaGetSymbolAddress((void**)&QS,  g_QS);
    cudaGetSymbolAddress((void**)&KS,  g_KS);
    cudaGetSymbolAddress((void**)&VS,  g_VS);
    cudaGetSymbolAddress((void**)&AS,  g_AS);
    cudaGetSymbolAddress((void**)&KVP, g_KVP);
    cudaGetSymbolAddress((void**)&KV,  g_KV);

    const int athreads = 256;
    const int ablocks = (BCN + athreads - 1) / athreads;

    // 1) alif on x, NCHW -> NHWC spikes
    alif_first_kernel<<<dim3(NN / 32, CC / 32, BB), dim3(32, 8)>>>(x, XS, vth);

    // 2) q/k/v branches (NHWC throughout)
    float* sp[3] = {QS, KS, VS};
    for (int i = 0; i < 3; i++) {
        run_branch(XS, i, BR, 1, w1, dw, pw,
                   b1w, b1b, b1m, b1v, b2w, b2b, b2m, b2v, b3w, b3b, b3m, b3v, PAD, DWB);
        alif_kernel<<<ablocks, athreads>>>(BR, sp[i], vth, 1 + i);
    }

    // 3) linear attention (exact fp32)
    kv_kernel<<<dim3(4, TT * BB * HEADS), 256>>>(KS, VS, KVP);
    kvred_kernel<<<(TT * BB * HEADS * DH * DH + 255) / 256, 256>>>(KVP, KV);
    av_kernel<<<dim3(64, TT * BB * HEADS), 256>>>(QS, KV, BR);
    alif_kernel<<<ablocks, athreads>>>(BR, AS, vth, 4);

    // 4) final branch -> d_out (NCHW)
    run_branch(AS, 3, out, 2, w1, dw, pw,
               b1w, b1b, b1m, b1v, b2w, b2b, b2m, b2v, b3w, b3b, b3m, b3v, PAD, DWB);
}